// round 10
// baseline (speedup 1.0000x reference)
#include <cuda_runtime.h>
#include <cuda_fp16.h>
#include <math.h>
#include <cstdint>

// ============================================================================
// Round 10: out = s_in @ Wfold + bfold (algebraic collapse, R2 derivation).
// Single fused kernel, fp16 m16n8k16, 1 CTA/SM x 704 threads (22 warps):
//  - in-kernel W fold + device-wide flag (all 148 CTAs co-resident)
//  - per-warp 8-stage x 1KB cp.async ring, 6 chunks in flight
//  - 16-row warp batches, NB=6250 over 3256 warps -> 96% utilization
//  - A-prologue issued before the fold, hiding fold+barrier latency
// ============================================================================

#define EPS_F 1e-6f

__device__ __half g_Wh[16384];    // fragment-major f16 W
__device__ int g_sync[2];         // [0]=batch counter, [1]=fold-done count

// ---------------- helpers ---------------------------------------------------
#define PACK_F16X2(d, hi, lo) \
    asm("cvt.rn.f16x2.f32 %0, %1, %2;" : "=r"(d) : "f"(hi), "f"(lo))

#define MMA_F16(c, a0, a1, a2, a3, b0, b1)                                      \
    asm volatile(                                                               \
        "mma.sync.aligned.m16n8k16.row.col.f32.f16.f16.f32 "                    \
        "{%0,%1,%2,%3}, {%4,%5,%6,%7}, {%8,%9}, {%0,%1,%2,%3};"                 \
        : "+f"((c)[0]), "+f"((c)[1]), "+f"((c)[2]), "+f"((c)[3])                \
        : "r"(a0), "r"(a1), "r"(a2), "r"(a3), "r"(b0), "r"(b1))

#define CP_ASYNC16(dst, src)                                                    \
    asm volatile("cp.async.cg.shared.global [%0], [%1], 16;"                    \
                 :: "r"(dst), "l"(src) : "memory")
#define CP_COMMIT()  asm volatile("cp.async.commit_group;" ::: "memory")
#define CP_WAIT(n)   asm volatile("cp.async.wait_group %0;" :: "n"(n) : "memory")

__device__ __forceinline__ uint32_t smem_u32(const void* p) {
    uint32_t a;
    asm("{ .reg .u64 t; cvta.to.shared.u64 t, %1; cvt.u32.u64 %0, t; }"
        : "=r"(a) : "l"(p));
    return a;
}

#define NWARP 22
#define NTHR  (NWARP * 32)
// smem u32 layout: [0..8191] W frags | [8192..8255] bias | rings 8KB/warp
#define RING0_U32 8256
#define SMEM_U32  (RING0_U32 + NWARP * 2048)   // 53312 u32 = 213248 B

// ---------------- fused persistent GEMM: [M,256] @ [256,64] -----------------
__global__ __launch_bounds__(NTHR, 1)
void mma_all(const float* __restrict__ A, float* __restrict__ C,
             const float* __restrict__ Wv, const float* __restrict__ bv,
             int M, int NB, float nf) {
    extern __shared__ uint32_t sm[];
    const uint32_t sb = smem_u32(sm);

    const int t = threadIdx.x;
    const int wid = t >> 5;
    const int lane = t & 31;
    const int g  = lane >> 2;
    const int kq = lane & 3;
    const float scale = nf / (8.f * (nf + EPS_F));

    // ring: 8 stages x 1024 B per warp; thread slot = g*64 + kq*16 bytes
    const uint32_t ring0 = sb + RING0_U32 * 4 + wid * 8192 + g * 64 + kq * 16;
    const float4* ringp = (const float4*)((const char*)sm +
                          RING0_U32 * 4 + wid * 8192 + g * 64 + kq * 16);
    // ringp in float4 units: stage*64 ; +32 for row g+8

#define SETUP_PTRS(p0, p1, base)                                                \
    const float* p0 = A + (size_t)min((base) + g,     M - 1) * 256 + kq * 4;    \
    const float* p1 = A + (size_t)min((base) + g + 8, M - 1) * 256 + kq * 4

#define LOAD_CHUNK(p0, p1, c, st) do {                                          \
        uint32_t d_ = ring0 + (st) * 1024;                                      \
        CP_ASYNC16(d_,       p0 + (c) * 16);                                    \
        CP_ASYNC16(d_ + 512, p1 + (c) * 16);                                    \
    } while (0)

    // ---- 1) grab first batch, issue A-prologue chunks 0..5 (6 groups) ----
    int b;
    if (lane == 0) b = atomicAdd(&g_sync[0], 1);
    b = __shfl_sync(0xffffffffu, b, 0);
    const bool have = (b < NB);

    if (have) {
        SETUP_PTRS(i0, i1, b * 16);
#pragma unroll
        for (int c = 0; c < 6; c++) { LOAD_CHUNK(i0, i1, c, c); CP_COMMIT(); }
    } else {
#pragma unroll
        for (int c = 0; c < 6; c++) CP_COMMIT();
    }

    // ---- 2) cooperative W fold: first 16384 global threads, 1 frag-half ----
    {
        int e = blockIdx.x * NTHR + t;
        if (e < 16384) {
            const int n = e & 63, k = e >> 6;
            float s = 0.f;
#pragma unroll
            for (int h = 0; h < 8; h++) s += Wv[k * 512 + h * 64 + n];
            const int c  = k >> 4;
            const int r  = k & 15;
            const int kk = r >> 2;
            const int s2 = (r >> 1) & 1;
            const int w  = k & 1;
            const int j  = n >> 3;
            const int ln = (n & 7) * 4 + kk;
            g_Wh[((((c * 8 + j) * 32) + ln) * 2 + s2) * 2 + w] =
                __float2half_rn(s * scale);
        }
    }
    __threadfence();
    __syncthreads();
    if (t == 0) atomicAdd(&g_sync[1], 1);

    // bias (local, no dependency on fold flag)
    if (t < 64) {
        float bsum = 0.f;
#pragma unroll
        for (int h = 0; h < 8; h++) bsum += bv[h * 64 + t];
        ((float*)(sm + 8192))[t] = bsum * scale;
    }

    // ---- 3) wait for all 148 CTAs' fold, then stage W (32 KB, L2-hot) ----
    if (t == 0) {
        while (((volatile int*)g_sync)[1] < (int)gridDim.x) __nanosleep(64);
    }
    __syncthreads();
    __threadfence();
    {
        uint32_t dst = sb;
        const char* src = (const char*)g_Wh;
        for (int e = t; e < 2048; e += NTHR)
            CP_ASYNC16(dst + e * 16, src + e * 16);
        CP_COMMIT();
    }
    CP_WAIT(0);
    __syncthreads();

    const uint2* Wp = ((const uint2*)sm) + lane;
    const float* bias_s = (const float*)(sm + 8192);

    // ---- 4) mainloop: 16 rows/batch, cross-batch pipelined, depth 6 ----
    if (have) {
        SETUP_PTRS(s0, s1, b * 16);
        const float *c0p = s0, *c1p = s1;
        uint32_t ldst = 6;   // next load stage (chunks 0..5 occupy 0..5)
        uint32_t rdst = 0;   // next read stage

        for (;;) {
            int bn = NB;
            const float *n0p = c0p, *n1p = c1p;

            float acc[8][4];
#pragma unroll
            for (int j = 0; j < 8; j++)
#pragma unroll
                for (int i = 0; i < 4; i++) acc[j][i] = 0.f;

#pragma unroll
            for (int c = 0; c < 16; c++) {
                if (c == 9) {
                    if (lane == 0) bn = atomicAdd(&g_sync[0], 1);
                    bn = __shfl_sync(0xffffffffu, bn, 0);
                }
                if (c == 10 && bn < NB) {
                    SETUP_PTRS(t0, t1, bn * 16);
                    n0p = t0; n1p = t1;
                }
                if (c < 10) {
                    LOAD_CHUNK(c0p, c1p, c + 6, ldst & 7); ldst++;
                } else if (bn < NB) {
                    LOAD_CHUNK(n0p, n1p, c - 10, ldst & 7); ldst++;
                }
                CP_COMMIT();
                CP_WAIT(6);

                const int st = rdst & 7; rdst++;
                float4 q0 = ringp[st * 64];
                float4 q1 = ringp[st * 64 + 32];

                uint32_t a0, a1, a2, a3;
                PACK_F16X2(a0, q0.y, q0.x); PACK_F16X2(a1, q1.y, q1.x);
                PACK_F16X2(a2, q0.w, q0.z); PACK_F16X2(a3, q1.w, q1.z);
#pragma unroll
                for (int j = 0; j < 8; j++) {
                    uint2 w2 = Wp[(c * 8 + j) * 32];
                    MMA_F16(acc[j], a0, a1, a2, a3, w2.x, w2.y);
                }
            }

            // epilogue: bias + store (rows b*16+g, +8)
            const int r0 = b * 16 + g;
            const int r1 = r0 + 8;
#pragma unroll
            for (int j = 0; j < 8; j++) {
                int col = j * 8 + kq * 2;
                float2 bb = *(const float2*)(bias_s + col);
                if (r0 < M)
                    *(float2*)(C + (size_t)r0 * 64 + col) =
                        make_float2(acc[j][0] + bb.x, acc[j][1] + bb.y);
                if (r1 < M)
                    *(float2*)(C + (size_t)r1 * 64 + col) =
                        make_float2(acc[j][2] + bb.x, acc[j][3] + bb.y);
            }

            if (bn >= NB) break;
            b = bn;
            c0p = n0p; c1p = n1p;
        }
    }
#undef LOAD_CHUNK
#undef SETUP_PTRS
}

// ---------------- launch ----------------------------------------------------
extern "C" void kernel_launch(void* const* d_in, const int* in_sizes, int n_in,
                              void* d_out, int out_size) {
    const float* s_in = (const float*)d_in[1];
    const float* Wv   = (const float*)d_in[6];
    const float* bv   = (const float*)d_in[7];
    float* out = (float*)d_out;

    const int M = in_sizes[0] / 256;
    const int NB = (M + 15) / 16;

    // reset batch counter + fold-done flag (stream-ordered before the kernel)
    void* pSync;
    cudaGetSymbolAddress(&pSync, g_sync);
    cudaMemsetAsync(pSync, 0, 2 * sizeof(int));

    const int SMEM = SMEM_U32 * 4;   // 213248 B -> 1 CTA/SM
    cudaFuncSetAttribute(mma_all,
                         cudaFuncAttributeMaxDynamicSharedMemorySize, SMEM);
    mma_all<<<148, NTHR, SMEM>>>(s_in, out, Wv, bv, M, NB, (float)M);
}